// round 1
// baseline (speedup 1.0000x reference)
#include <cuda_runtime.h>

#define H 1024
#define T 20

// Scratch (alloc-free rule: __device__ globals). All fully written before read.
__device__ float g_h1[H];        // enc layer1 output at t=0, batch 4095  == last[0]
__device__ float g_d0[T * H];    // dec layer0 outputs, t-major
__device__ float g_d1[T * H];    // dec layer1 outputs, t-major

__device__ __forceinline__ float warp_reduce(float v) {
#pragma unroll
    for (int o = 16; o; o >>= 1) v += __shfl_xor_sync(0xffffffffu, v, o);
    return v;
}

// K1: h0 = relu(enc_w0 @ x[0,4095] + b0) in smem; h1 = relu(enc_w1 @ h0 + b1).
// 128 blocks x 256 threads, warp-per-output-row.
__global__ void k1_enc(const float* __restrict__ x,
                       const float* __restrict__ w0, const float* __restrict__ b0,
                       const float* __restrict__ w1, const float* __restrict__ b1) {
    __shared__ float s_h0[H];
    // x: (20, 4096, 2) row-major; x[0, 4095, :] at flat 8190, 8191
    const float x0 = x[8190], x1 = x[8191];
    for (int i = threadIdx.x; i < H; i += 256) {
        float v = fmaf(w0[2 * i], x0, fmaf(w0[2 * i + 1], x1, b0[i]));
        s_h0[i] = fmaxf(v, 0.0f);
    }
    __syncthreads();
    const int warp = threadIdx.x >> 5, lane = threadIdx.x & 31;
    const int h = blockIdx.x * 8 + warp;
    const float4* wrow = (const float4*)(w1 + (size_t)h * H);
    const float4* s4 = (const float4*)s_h0;
    float acc = 0.0f;
#pragma unroll
    for (int j = 0; j < 8; j++) {
        const int c = j * 32 + lane;
        float4 a = __ldg(wrow + c);
        float4 v = s4[c];
        acc = fmaf(a.x, v.x, acc); acc = fmaf(a.y, v.y, acc);
        acc = fmaf(a.z, v.z, acc); acc = fmaf(a.w, v.w, acc);
    }
    acc = warp_reduce(acc);
    if (lane == 0) g_h1[h] = fmaxf(acc + b1[h], 0.0f);
}

// K2: pre = dec_w0 @ h1 + b (matvec, warp-per-row); then per-channel 20-step
// IndRNN scan (input is time-constant) -> g_d0.
__global__ void k2_dec0(const float* __restrict__ w, const float* __restrict__ b,
                        const float* __restrict__ u) {
    __shared__ float s[H];
    for (int i = threadIdx.x; i < H; i += 256) s[i] = g_h1[i];
    __syncthreads();
    const int warp = threadIdx.x >> 5, lane = threadIdx.x & 31;
    const int g = blockIdx.x * 8 + warp;
    const float4* wrow = (const float4*)(w + (size_t)g * H);
    const float4* s4 = (const float4*)s;
    float acc = 0.0f;
#pragma unroll
    for (int j = 0; j < 8; j++) {
        const int c = j * 32 + lane;
        float4 a = __ldg(wrow + c);
        float4 v = s4[c];
        acc = fmaf(a.x, v.x, acc); acc = fmaf(a.y, v.y, acc);
        acc = fmaf(a.z, v.z, acc); acc = fmaf(a.w, v.w, acc);
    }
    acc = warp_reduce(acc);
    if (lane == 0) {
        const float pre = acc + b[g];
        const float uu = u[g];
        float d = 0.0f;
#pragma unroll
        for (int t = 0; t < T; t++) {
            d = fmaxf(fmaf(uu, d, pre), 0.0f);
            g_d0[t * H + g] = d;
        }
    }
}

// K3: pre1[t][h] = dec_w1[h] . d0[t] + b[h] for all t in parallel (GEMM 20x1024x1024),
// 2 rows x 20 t register-blocked per warp; then per-channel dec1 scan -> g_d1.
// 128 blocks x 128 threads (4 warps, 8 rows/block).
__global__ void __launch_bounds__(128) k3_dec1(const float* __restrict__ w,
                                               const float* __restrict__ b,
                                               const float* __restrict__ u) {
    const int warp = threadIdx.x >> 5, lane = threadIdx.x & 31;
    const int h0 = blockIdx.x * 8 + warp * 2;
    const float4* w0r = (const float4*)(w + (size_t)h0 * H);
    const float4* w1r = (const float4*)(w + (size_t)(h0 + 1) * H);
    const float4* d04 = (const float4*)g_d0;

    float acc0[T], acc1[T];
#pragma unroll
    for (int t = 0; t < T; t++) { acc0[t] = 0.0f; acc1[t] = 0.0f; }

#pragma unroll
    for (int j = 0; j < 8; j++) {
        const int c = j * 32 + lane;
        float4 a = __ldg(w0r + c);
        float4 q = __ldg(w1r + c);
#pragma unroll
        for (int t = 0; t < T; t++) {
            float4 v = __ldg(d04 + t * (H / 4) + c);
            acc0[t] = fmaf(a.x, v.x, acc0[t]); acc0[t] = fmaf(a.y, v.y, acc0[t]);
            acc0[t] = fmaf(a.z, v.z, acc0[t]); acc0[t] = fmaf(a.w, v.w, acc0[t]);
            acc1[t] = fmaf(q.x, v.x, acc1[t]); acc1[t] = fmaf(q.y, v.y, acc1[t]);
            acc1[t] = fmaf(q.z, v.z, acc1[t]); acc1[t] = fmaf(q.w, v.w, acc1[t]);
        }
    }
#pragma unroll
    for (int t = 0; t < T; t++) {
        acc0[t] = warp_reduce(acc0[t]);   // butterfly: all lanes hold the sum
        acc1[t] = warp_reduce(acc1[t]);
    }
    if (lane == 0) {
        const float bb = b[h0], uu = u[h0];
        float d = 0.0f;
#pragma unroll
        for (int t = 0; t < T; t++) {
            d = fmaxf(fmaf(uu, d, acc0[t] + bb), 0.0f);
            g_d1[t * H + h0] = d;
        }
    }
    if (lane == 1) {
        const float bb = b[h0 + 1], uu = u[h0 + 1];
        float d = 0.0f;
#pragma unroll
        for (int t = 0; t < T; t++) {
            d = fmaxf(fmaf(uu, d, acc1[t] + bb), 0.0f);
            g_d1[t * H + h0 + 1] = d;
        }
    }
}

// K4: predict[t,k] = out_w[k] . d1[t] + out_b[k]  (40 outputs). One block, 32 warps.
__global__ void k4_out(const float* __restrict__ ow, const float* __restrict__ ob,
                       float* __restrict__ out) {
    const int warp = threadIdx.x >> 5, lane = threadIdx.x & 31;
    for (int o = warp; o < 2 * T; o += 32) {
        const int t = o >> 1, k = o & 1;
        const float4* wr = (const float4*)(ow + (size_t)k * H);
        const float4* dr = (const float4*)(g_d1 + (size_t)t * H);
        float acc = 0.0f;
#pragma unroll
        for (int j = 0; j < 8; j++) {
            const int c = j * 32 + lane;
            float4 a = __ldg(wr + c);
            float4 v = __ldg(dr + c);
            acc = fmaf(a.x, v.x, acc); acc = fmaf(a.y, v.y, acc);
            acc = fmaf(a.z, v.z, acc); acc = fmaf(a.w, v.w, acc);
        }
        acc = warp_reduce(acc);
        if (lane == 0) out[o] = acc + ob[k];
    }
}

extern "C" void kernel_launch(void* const* d_in, const int* in_sizes, int n_in,
                              void* d_out, int out_size) {
    const float* x      = (const float*)d_in[0];
    const float* enc_w0 = (const float*)d_in[1];
    // d_in[2] = enc_u0: unused (only t=0 encoder state needed, h_{-1}=0)
    const float* enc_b0 = (const float*)d_in[3];
    const float* enc_w1 = (const float*)d_in[4];
    // d_in[5] = enc_u1: unused
    const float* enc_b1 = (const float*)d_in[6];
    const float* dec_w0 = (const float*)d_in[7];
    const float* dec_u0 = (const float*)d_in[8];
    const float* dec_b0 = (const float*)d_in[9];
    const float* dec_w1 = (const float*)d_in[10];
    const float* dec_u1 = (const float*)d_in[11];
    const float* dec_b1 = (const float*)d_in[12];
    const float* out_w  = (const float*)d_in[13];
    const float* out_b  = (const float*)d_in[14];
    float* out = (float*)d_out;

    k1_enc <<<128, 256>>>(x, enc_w0, enc_b0, enc_w1, enc_b1);
    k2_dec0<<<128, 256>>>(dec_w0, dec_b0, dec_u0);
    k3_dec1<<<128, 128>>>(dec_w1, dec_b1, dec_u1);
    k4_out <<<1, 1024>>>(out_w, out_b, out);
}

// round 3
// speedup vs baseline: 1.1712x; 1.1712x over previous
#include <cuda_runtime.h>

#define H 1024
#define T 20
#define GRID 128
#define BLK 256

// Scratch (__device__ globals per alloc-free rule). Fully written before read.
__device__ float g_h1[H];        // enc layer1 output at t=0, batch 4095 == last[0]
__device__ float g_d0[T * H];    // dec layer0 outputs, t-major
__device__ float g_d1[T * H];    // dec layer1 outputs, t-major
__device__ unsigned g_cnt = 0;   // barrier arrival counter (self-resets each use)
__device__ unsigned g_gen = 0;   // barrier generation (monotonic; graph-replay safe)

__device__ __forceinline__ float warp_reduce(float v) {
#pragma unroll
    for (int o = 16; o; o >>= 1) v += __shfl_xor_sync(0xffffffffu, v, o);
    return v;
}

// Sense-reversal grid barrier. GRID=128 <= 148 SMs at 1 block/SM -> all blocks
// co-resident in one wave, spin is deadlock-free. Counter self-resets each use.
__device__ __forceinline__ void grid_barrier() {
    __syncthreads();
    if (threadIdx.x == 0) {
        __threadfence();                                  // release our block's writes
        unsigned gen = *(volatile unsigned*)&g_gen;
        if (atomicAdd(&g_cnt, 1u) == GRID - 1) {
            g_cnt = 0;
            __threadfence();
            atomicAdd(&g_gen, 1u);
        } else {
            while (*(volatile unsigned*)&g_gen == gen) {}
        }
        __threadfence();                                  // acquire others' writes
    }
    __syncthreads();
}

// Warp-per-row matvec over a 1024-vector staged in smem. Weight row is a true
// kernel-constant input -> __ldg is safe there.
__device__ __forceinline__ float dot_row_smem(const float* __restrict__ wrow,
                                              const float4* __restrict__ s4, int lane) {
    const float4* w4 = (const float4*)wrow;
    float acc = 0.0f;
#pragma unroll
    for (int j = 0; j < 8; j++) {
        const int c = j * 32 + lane;
        float4 a = __ldg(w4 + c);
        float4 v = s4[c];
        acc = fmaf(a.x, v.x, acc); acc = fmaf(a.y, v.y, acc);
        acc = fmaf(a.z, v.z, acc); acc = fmaf(a.w, v.w, acc);
    }
    return warp_reduce(acc);
}

__global__ void __launch_bounds__(BLK) fused_net(
    const float* __restrict__ x,
    const float* __restrict__ enc_w0, const float* __restrict__ enc_b0,
    const float* __restrict__ enc_w1, const float* __restrict__ enc_b1,
    const float* __restrict__ dec_w0, const float* __restrict__ dec_u0,
    const float* __restrict__ dec_b0,
    const float* __restrict__ dec_w1, const float* __restrict__ dec_u1,
    const float* __restrict__ dec_b1,
    const float* __restrict__ out_w, const float* __restrict__ out_b,
    float* __restrict__ out)
{
    __shared__ float s_vec[H];       // staged vector for matvec phases
    __shared__ float s_pre[8][T];    // dec1 pre-activations for this block's 8 rows

    const int warp = threadIdx.x >> 5, lane = threadIdx.x & 31;

    // ---- Phase 1: h0 = relu(enc_w0 @ x[0,4095] + b0) (redundant per block, trivial);
    //      h1 = relu(enc_w1 @ h0 + b1), warp-per-row, 8 rows/block.
    {
        // x: (20, 4096, 2); x[0, 4095, :] at flat {8190, 8191}. h_{-1}=0 => enc_u unused.
        const float x0 = x[8190], x1 = x[8191];
        for (int i = threadIdx.x; i < H; i += BLK) {
            float v = fmaf(enc_w0[2 * i], x0, fmaf(enc_w0[2 * i + 1], x1, enc_b0[i]));
            s_vec[i] = fmaxf(v, 0.0f);
        }
        __syncthreads();
        const int h = blockIdx.x * 8 + warp;
        float acc = dot_row_smem(enc_w1 + (size_t)h * H, (const float4*)s_vec, lane);
        if (lane == 0) g_h1[h] = fmaxf(acc + enc_b1[h], 0.0f);
    }
    grid_barrier();

    // ---- Phase 2: pre = dec_w0 @ h1 + b (warp-per-row); 20-step elementwise IndRNN
    //      scan with time-constant input -> g_d0.
    {
        // COHERENT loads of g_h1 (written this launch by other SMs).
        for (int i = threadIdx.x; i < H; i += BLK) s_vec[i] = g_h1[i];
        __syncthreads();
        const int g = blockIdx.x * 8 + warp;
        float acc = dot_row_smem(dec_w0 + (size_t)g * H, (const float4*)s_vec, lane);
        if (lane == 0) {
            const float pre = acc + dec_b0[g];
            const float uu = dec_u0[g];
            float d = 0.0f;
#pragma unroll
            for (int t = 0; t < T; t++) {
                d = fmaxf(fmaf(uu, d, pre), 0.0f);
                g_d0[t * H + g] = d;
            }
        }
    }
    grid_barrier();

    // ---- Phase 3: pre1[t][h] = dec_w1[h] . d0[t] + b[h]  (GEMM 20x1024x1024).
    // 8 warps = 4 row-pairs x 2 t-halves: 2 rows x 10 timesteps per warp.
    // g_d0 read with PLAIN coherent loads (NOT __ldg: written this launch).
    {
        const int rp = warp & 3;           // row pair within block's 8 rows
        const int th = warp >> 2;          // t-half: 0 -> t[0,10), 1 -> t[10,20)
        const int h0 = blockIdx.x * 8 + rp * 2;
        const float4* w0r = (const float4*)(dec_w1 + (size_t)h0 * H);
        const float4* w1r = w0r + (H / 4);
        const float4* d04 = (const float4*)g_d0 + th * 10 * (H / 4);

        float acc0[10], acc1[10];
#pragma unroll
        for (int t = 0; t < 10; t++) { acc0[t] = 0.0f; acc1[t] = 0.0f; }

#pragma unroll
        for (int j = 0; j < 8; j++) {
            const int c = j * 32 + lane;
            float4 a = __ldg(w0r + c);     // weights: kernel-constant, __ldg OK
            float4 q = __ldg(w1r + c);
#pragma unroll
            for (int t = 0; t < 10; t++) {
                float4 v = d04[t * (H / 4) + c];   // coherent load; L1 reuse in-phase
                acc0[t] = fmaf(a.x, v.x, acc0[t]); acc0[t] = fmaf(a.y, v.y, acc0[t]);
                acc0[t] = fmaf(a.z, v.z, acc0[t]); acc0[t] = fmaf(a.w, v.w, acc0[t]);
                acc1[t] = fmaf(q.x, v.x, acc1[t]); acc1[t] = fmaf(q.y, v.y, acc1[t]);
                acc1[t] = fmaf(q.z, v.z, acc1[t]); acc1[t] = fmaf(q.w, v.w, acc1[t]);
            }
        }
#pragma unroll
        for (int t = 0; t < 10; t++) {
            acc0[t] = warp_reduce(acc0[t]);   // butterfly: every lane holds the sum
            acc1[t] = warp_reduce(acc1[t]);
        }
        if (lane == 0) {
#pragma unroll
            for (int t = 0; t < 10; t++) s_pre[rp * 2][th * 10 + t] = acc0[t];
        }
        if (lane == 1) {
#pragma unroll
            for (int t = 0; t < 10; t++) s_pre[rp * 2 + 1][th * 10 + t] = acc1[t];
        }
        __syncthreads();
        if (threadIdx.x < 8) {
            const int h = blockIdx.x * 8 + threadIdx.x;
            const float bb = dec_b1[h], uu = dec_u1[h];
            float d = 0.0f;
#pragma unroll
            for (int t = 0; t < T; t++) {
                d = fmaxf(fmaf(uu, d, s_pre[threadIdx.x][t] + bb), 0.0f);
                g_d1[t * H + h] = d;
            }
        }
    }
    grid_barrier();

    // ---- Phase 4: predict[t,k] = out_w[k] . d1[t] + out_b[k]. 40 outputs over
    //      5 blocks x 8 warps (warp-per-output). g_d1 read coherently.
    if (blockIdx.x < 5) {
        const int o = blockIdx.x * 8 + warp;          // 0..39, == t*2+k
        const int t = o >> 1, k = o & 1;
        const float4* wr = (const float4*)(out_w + (size_t)k * H);
        const float4* dr = (const float4*)(g_d1 + (size_t)t * H);
        float acc = 0.0f;
#pragma unroll
        for (int j = 0; j < 8; j++) {
            const int c = j * 32 + lane;
            float4 a = __ldg(wr + c);
            float4 v = dr[c];                          // coherent load
            acc = fmaf(a.x, v.x, acc); acc = fmaf(a.y, v.y, acc);
            acc = fmaf(a.z, v.z, acc); acc = fmaf(a.w, v.w, acc);
        }
        acc = warp_reduce(acc);
        if (lane == 0) out[o] = acc + out_b[k];
    }
}

extern "C" void kernel_launch(void* const* d_in, const int* in_sizes, int n_in,
                              void* d_out, int out_size) {
    const float* x      = (const float*)d_in[0];
    const float* enc_w0 = (const float*)d_in[1];
    // d_in[2] = enc_u0: unused (only t=0 encoder state needed, h_{-1}=0)
    const float* enc_b0 = (const float*)d_in[3];
    const float* enc_w1 = (const float*)d_in[4];
    // d_in[5] = enc_u1: unused
    const float* enc_b1 = (const float*)d_in[6];
    const float* dec_w0 = (const float*)d_in[7];
    const float* dec_u0 = (const float*)d_in[8];
    const float* dec_b0 = (const float*)d_in[9];
    const float* dec_w1 = (const float*)d_in[10];
    const float* dec_u1 = (const float*)d_in[11];
    const float* dec_b1 = (const float*)d_in[12];
    const float* out_w  = (const float*)d_in[13];
    const float* out_b  = (const float*)d_in[14];
    float* out = (float*)d_out;

    fused_net<<<GRID, BLK>>>(x, enc_w0, enc_b0, enc_w1, enc_b1,
                             dec_w0, dec_u0, dec_b0,
                             dec_w1, dec_u1, dec_b1,
                             out_w, out_b, out);
}

// round 4
// speedup vs baseline: 1.6561x; 1.4140x over previous
#include <cuda_runtime.h>

#define H 1024
#define T 20
#define GRID 128
#define BLK 256

// Scratch (__device__ globals per alloc-free rule). Fully written before read.
__device__ float g_h1[H];        // enc layer1 output at t=0, batch 4095 == last[0]
__device__ float g_d0[T * H];    // dec layer0 outputs, t-major
__device__ float g_d1[T * H];    // dec layer1 outputs, t-major
__device__ unsigned g_cnt = 0;   // barrier arrival counter (self-resets each use)
__device__ unsigned g_gen = 0;   // barrier generation (monotonic; graph-replay safe)

__device__ __forceinline__ float warp_reduce(float v) {
#pragma unroll
    for (int o = 16; o; o >>= 1) v += __shfl_xor_sync(0xffffffffu, v, o);
    return v;
}

__device__ __forceinline__ void l2_prefetch(const void* p) {
    asm volatile("prefetch.global.L2 [%0];" :: "l"(p));
}

// Sense-reversal grid barrier. GRID=128 <= 148 SMs at 1 block/SM -> all blocks
// co-resident in one wave, spin is deadlock-free. Counter self-resets each use.
__device__ __forceinline__ void grid_barrier() {
    __syncthreads();
    if (threadIdx.x == 0) {
        __threadfence();                                  // release our block's writes
        unsigned gen = *(volatile unsigned*)&g_gen;
        if (atomicAdd(&g_cnt, 1u) == GRID - 1) {
            g_cnt = 0;
            __threadfence();
            atomicAdd(&g_gen, 1u);
        } else {
            while (*(volatile unsigned*)&g_gen == gen) {}
        }
        __threadfence();                                  // acquire others' writes
    }
    __syncthreads();
}

// Warp-per-row matvec over a 1024-vector staged in smem. Weight row is a true
// kernel-constant input -> __ldg is safe there.
__device__ __forceinline__ float dot_row_smem(const float* __restrict__ wrow,
                                              const float4* __restrict__ s4, int lane) {
    const float4* w4 = (const float4*)wrow;
    float acc = 0.0f;
#pragma unroll
    for (int j = 0; j < 8; j++) {
        const int c = j * 32 + lane;
        float4 a = __ldg(w4 + c);
        float4 v = s4[c];
        acc = fmaf(a.x, v.x, acc); acc = fmaf(a.y, v.y, acc);
        acc = fmaf(a.z, v.z, acc); acc = fmaf(a.w, v.w, acc);
    }
    return warp_reduce(acc);
}

__global__ void __launch_bounds__(BLK, 1) fused_net(
    const float* __restrict__ x,
    const float* __restrict__ enc_w0, const float* __restrict__ enc_b0,
    const float* __restrict__ enc_w1, const float* __restrict__ enc_b1,
    const float* __restrict__ dec_w0, const float* __restrict__ dec_u0,
    const float* __restrict__ dec_b0,
    const float* __restrict__ dec_w1, const float* __restrict__ dec_u1,
    const float* __restrict__ dec_b1,
    const float* __restrict__ out_w, const float* __restrict__ out_b,
    float* __restrict__ out)
{
    __shared__ float s_vec[H];       // staged vector for matvec phases
    __shared__ float s_pre[8][T];    // dec1 pre-activations for this block's 8 rows

    const int warp = threadIdx.x >> 5, lane = threadIdx.x & 31;

    // ---- L2 prefetch of later-phase weights for this block's rows (overlaps
    //      phase 1). dec_w0/dec_w1 rows [8*bid, 8*bid+8): 32KB each -> 256 lines
    //      each; 2 lines per thread per matrix.
    {
        const size_t row0 = (size_t)blockIdx.x * 8 * H;   // floats
        const char* p0 = (const char*)(dec_w0 + row0);
        const char* p1 = (const char*)(dec_w1 + row0);
        l2_prefetch(p0 + (size_t)threadIdx.x * 128);
        l2_prefetch(p0 + (size_t)(threadIdx.x + 256) * 128);
        l2_prefetch(p1 + (size_t)threadIdx.x * 128);
        l2_prefetch(p1 + (size_t)(threadIdx.x + 256) * 128);
        if (blockIdx.x < 5 && threadIdx.x < 64)           // out_w: 8KB
            l2_prefetch((const char*)out_w + (size_t)threadIdx.x * 128);
    }

    // ---- Phase 1: h0 = relu(enc_w0 @ x[0,4095] + b0) (redundant per block, trivial);
    //      h1 = relu(enc_w1 @ h0 + b1), warp-per-row, 8 rows/block.
    {
        // x: (20, 4096, 2); x[0, 4095, :] at flat {8190, 8191}. h_{-1}=0 => enc_u unused.
        const float x0 = x[8190], x1 = x[8191];
        for (int i = threadIdx.x; i < H; i += BLK) {
            float v = fmaf(enc_w0[2 * i], x0, fmaf(enc_w0[2 * i + 1], x1, enc_b0[i]));
            s_vec[i] = fmaxf(v, 0.0f);
        }
        __syncthreads();
        const int h = blockIdx.x * 8 + warp;
        float acc = dot_row_smem(enc_w1 + (size_t)h * H, (const float4*)s_vec, lane);
        if (lane == 0) g_h1[h] = fmaxf(acc + enc_b1[h], 0.0f);
    }
    grid_barrier();

    // ---- Phase 2: pre = dec_w0 @ h1 + b (warp-per-row); 20-step elementwise IndRNN
    //      scan with time-constant input -> g_d0.
    {
        for (int i = threadIdx.x; i < H; i += BLK) s_vec[i] = g_h1[i];   // coherent
        __syncthreads();
        const int g = blockIdx.x * 8 + warp;
        float acc = dot_row_smem(dec_w0 + (size_t)g * H, (const float4*)s_vec, lane);
        if (lane == 0) {
            const float pre = acc + dec_b0[g];
            const float uu = dec_u0[g];
            float d = 0.0f;
#pragma unroll
            for (int t = 0; t < T; t++) {
                d = fmaxf(fmaf(uu, d, pre), 0.0f);
                g_d0[t * H + g] = d;
            }
        }
    }
    grid_barrier();

    // ---- Phase 3: pre1[t][h] = dec_w1[h] . d0[t] + b[h]  (GEMM 20x1024x1024).
    // 8 warps = 4 row-pairs x 2 t-halves: 2 rows x 10 timesteps per warp.
    // Per j: batch-load 2 weight + 10 d0 float4s (12 independent LDG.128, MLP=12),
    // then 80 FMAs. Needs ~110 regs -> launch_bounds(256,1) grants them (no spill).
    {
        const int rp = warp & 3;           // row pair within block's 8 rows
        const int th = warp >> 2;          // t-half: 0 -> t[0,10), 1 -> t[10,20)
        const int h0 = blockIdx.x * 8 + rp * 2;
        const float4* w0r = (const float4*)(dec_w1 + (size_t)h0 * H);
        const float4* w1r = w0r + (H / 4);
        const float4* d04 = (const float4*)g_d0 + th * 10 * (H / 4);   // coherent

        float acc0[10], acc1[10];
#pragma unroll
        for (int t = 0; t < 10; t++) { acc0[t] = 0.0f; acc1[t] = 0.0f; }

#pragma unroll
        for (int j = 0; j < 8; j++) {
            const int c = j * 32 + lane;
            float4 a = __ldg(w0r + c);     // weights: kernel-constant, __ldg OK
            float4 q = __ldg(w1r + c);
            float4 v[10];
#pragma unroll
            for (int t = 0; t < 10; t++) v[t] = d04[t * (H / 4) + c];
#pragma unroll
            for (int t = 0; t < 10; t++) {
                acc0[t] = fmaf(a.x, v[t].x, acc0[t]); acc0[t] = fmaf(a.y, v[t].y, acc0[t]);
                acc0[t] = fmaf(a.z, v[t].z, acc0[t]); acc0[t] = fmaf(a.w, v[t].w, acc0[t]);
                acc1[t] = fmaf(q.x, v[t].x, acc1[t]); acc1[t] = fmaf(q.y, v[t].y, acc1[t]);
                acc1[t] = fmaf(q.z, v[t].z, acc1[t]); acc1[t] = fmaf(q.w, v[t].w, acc1[t]);
            }
        }
#pragma unroll
        for (int t = 0; t < 10; t++) {
            acc0[t] = warp_reduce(acc0[t]);   // butterfly: every lane holds the sum
            acc1[t] = warp_reduce(acc1[t]);
        }
        if (lane == 0) {
#pragma unroll
            for (int t = 0; t < 10; t++) s_pre[rp * 2][th * 10 + t] = acc0[t];
        }
        if (lane == 1) {
#pragma unroll
            for (int t = 0; t < 10; t++) s_pre[rp * 2 + 1][th * 10 + t] = acc1[t];
        }
        __syncthreads();
        if (threadIdx.x < 8) {
            const int h = blockIdx.x * 8 + threadIdx.x;
            const float bb = dec_b1[h], uu = dec_u1[h];
            float d = 0.0f;
#pragma unroll
            for (int t = 0; t < T; t++) {
                d = fmaxf(fmaf(uu, d, s_pre[threadIdx.x][t] + bb), 0.0f);
                g_d1[t * H + h] = d;
            }
        }
    }
    grid_barrier();

    // ---- Phase 4: predict[t,k] = out_w[k] . d1[t] + out_b[k]. 40 outputs over
    //      5 blocks x 8 warps (warp-per-output). g_d1 read coherently.
    if (blockIdx.x < 5) {
        const int o = blockIdx.x * 8 + warp;          // 0..39, == t*2+k
        const int t = o >> 1, k = o & 1;
        const float4* wr = (const float4*)(out_w + (size_t)k * H);
        const float4* dr = (const float4*)(g_d1 + (size_t)t * H);
        float acc = 0.0f;
#pragma unroll
        for (int j = 0; j < 8; j++) {
            const int c = j * 32 + lane;
            float4 a = __ldg(wr + c);
            float4 v = dr[c];                          // coherent load
            acc = fmaf(a.x, v.x, acc); acc = fmaf(a.y, v.y, acc);
            acc = fmaf(a.z, v.z, acc); acc = fmaf(a.w, v.w, acc);
        }
        acc = warp_reduce(acc);
        if (lane == 0) out[o] = acc + out_b[k];
    }
}

extern "C" void kernel_launch(void* const* d_in, const int* in_sizes, int n_in,
                              void* d_out, int out_size) {
    const float* x      = (const float*)d_in[0];
    const float* enc_w0 = (const float*)d_in[1];
    // d_in[2] = enc_u0: unused (only t=0 encoder state needed, h_{-1}=0)
    const float* enc_b0 = (const float*)d_in[3];
    const float* enc_w1 = (const float*)d_in[4];
    // d_in[5] = enc_u1: unused
    const float* enc_b1 = (const float*)d_in[6];
    const float* dec_w0 = (const float*)d_in[7];
    const float* dec_u0 = (const float*)d_in[8];
    const float* dec_b0 = (const float*)d_in[9];
    const float* dec_w1 = (const float*)d_in[10];
    const float* dec_u1 = (const float*)d_in[11];
    const float* dec_b1 = (const float*)d_in[12];
    const float* out_w  = (const float*)d_in[13];
    const float* out_b  = (const float*)d_in[14];
    float* out = (float*)d_out;

    fused_net<<<GRID, BLK>>>(x, enc_w0, enc_b0, enc_w1, enc_b1,
                             dec_w0, dec_u0, dec_b0,
                             dec_w1, dec_u1, dec_b1,
                             out_w, out_b, out);
}

// round 5
// speedup vs baseline: 1.8507x; 1.1175x over previous
#include <cuda_runtime.h>

#define H 1024
#define T 20
#define GRID 128
#define BLK 512

// Scratch (__device__ globals per alloc-free rule). Fully written before read.
__device__ float g_h1[H];        // enc layer1 output at t=0, batch 4095 == last[0]
__device__ float g_d0[T * H];    // dec layer0 outputs, t-major
__device__ float g_d1[T * H];    // dec layer1 outputs, t-major
__device__ unsigned g_cnt = 0;   // barrier arrival counter (self-resets each use)
__device__ unsigned g_gen = 0;   // barrier generation (monotonic; graph-replay safe)

__device__ __forceinline__ float warp_reduce(float v) {
#pragma unroll
    for (int o = 16; o; o >>= 1) v += __shfl_xor_sync(0xffffffffu, v, o);
    return v;
}

__device__ __forceinline__ void l2_prefetch(const void* p) {
    asm volatile("prefetch.global.L2 [%0];" :: "l"(p));
}

// Sense-reversal grid barrier. GRID=128 <= 148 SMs at 1 block/SM -> all blocks
// co-resident in one wave, spin is deadlock-free. Counter self-resets each use.
__device__ __forceinline__ void grid_barrier() {
    __syncthreads();
    if (threadIdx.x == 0) {
        __threadfence();                                  // release our block's writes
        unsigned gen = *(volatile unsigned*)&g_gen;
        if (atomicAdd(&g_cnt, 1u) == GRID - 1) {
            g_cnt = 0;
            __threadfence();
            atomicAdd(&g_gen, 1u);
        } else {
            while (*(volatile unsigned*)&g_gen == gen) {}
        }
        __threadfence();                                  // acquire others' writes
    }
    __syncthreads();
}

__global__ void __launch_bounds__(BLK, 1) fused_net(
    const float* __restrict__ x,
    const float* __restrict__ enc_w0, const float* __restrict__ enc_b0,
    const float* __restrict__ enc_w1, const float* __restrict__ enc_b1,
    const float* __restrict__ dec_w0, const float* __restrict__ dec_u0,
    const float* __restrict__ dec_b0,
    const float* __restrict__ dec_w1, const float* __restrict__ dec_u1,
    const float* __restrict__ dec_b1,
    const float* __restrict__ out_w, const float* __restrict__ out_b,
    float* __restrict__ out)
{
    __shared__ float s_vec[H];       // staged vector for matvec phases
    __shared__ float s_part[16];     // per-warp partial dot sums
    __shared__ float s_pre[8][T];    // dec1 pre-activations for this block's 8 rows

    const int tid = threadIdx.x;
    const int warp = tid >> 5, lane = tid & 31;
    const int row = warp & 7;        // phases 1/2/4: row (or output) index in block
    const int half = warp >> 3;      // phases 1/2/4: K-half (0: [0,512), 1: [512,1024))
    const int h = blockIdx.x * 8 + row;

    // L2 prefetch of phase-3/4 weights (dec_w0 is register-preloaded instead;
    // enc_w1 is demand-loaded immediately below).
    if (tid < 256)
        l2_prefetch((const char*)(dec_w1 + (size_t)blockIdx.x * 8 * H) + (size_t)tid * 128);
    if (blockIdx.x < 5 && tid < 64)
        l2_prefetch((const char*)out_w + (size_t)tid * 128);

    // ---- Phase 1: h1 = relu(enc_w1 @ relu(enc_w0 @ x[0,4095] + b0) + b1).
    // enc_w1 half-row preloaded BEFORE h0 compute -> DRAM latency overlapped.
    float4 wa, wb, wc, wd;
    {
        const float4* w1p = (const float4*)(enc_w1 + (size_t)h * H) + half * 128;
        wa = __ldg(w1p + lane);
        wb = __ldg(w1p + 32 + lane);
        wc = __ldg(w1p + 64 + lane);
        wd = __ldg(w1p + 96 + lane);
    }
    {
        // x: (20, 4096, 2); x[0, 4095, :] at flat {8190, 8191}. h_{-1}=0 => enc_u unused.
        const float x0 = x[8190], x1 = x[8191];
#pragma unroll
        for (int i = tid; i < H; i += BLK) {
            float v = fmaf(enc_w0[2 * i], x0, fmaf(enc_w0[2 * i + 1], x1, enc_b0[i]));
            s_vec[i] = fmaxf(v, 0.0f);
        }
        __syncthreads();
        const float4* s4 = (const float4*)s_vec + half * 128;
        float4 v0 = s4[lane], v1 = s4[32 + lane], v2 = s4[64 + lane], v3 = s4[96 + lane];
        float acc = 0.0f;
        acc = fmaf(wa.x, v0.x, acc); acc = fmaf(wa.y, v0.y, acc);
        acc = fmaf(wa.z, v0.z, acc); acc = fmaf(wa.w, v0.w, acc);
        acc = fmaf(wb.x, v1.x, acc); acc = fmaf(wb.y, v1.y, acc);
        acc = fmaf(wb.z, v1.z, acc); acc = fmaf(wb.w, v1.w, acc);
        acc = fmaf(wc.x, v2.x, acc); acc = fmaf(wc.y, v2.y, acc);
        acc = fmaf(wc.z, v2.z, acc); acc = fmaf(wc.w, v2.w, acc);
        acc = fmaf(wd.x, v3.x, acc); acc = fmaf(wd.y, v3.y, acc);
        acc = fmaf(wd.z, v3.z, acc); acc = fmaf(wd.w, v3.w, acc);
        acc = warp_reduce(acc);
        if (lane == 0) s_part[warp] = acc;
    }
    // Preload dec_w0 half-row NOW: its DRAM latency hides under the grid barrier.
    {
        const float4* w0p = (const float4*)(dec_w0 + (size_t)h * H) + half * 128;
        wa = __ldg(w0p + lane);
        wb = __ldg(w0p + 32 + lane);
        wc = __ldg(w0p + 64 + lane);
        wd = __ldg(w0p + 96 + lane);
    }
    __syncthreads();
    if (tid < 8)
        g_h1[blockIdx.x * 8 + tid] =
            fmaxf(s_part[tid] + s_part[tid + 8] + enc_b1[blockIdx.x * 8 + tid], 0.0f);
    grid_barrier();

    // ---- Phase 2: pre = dec_w0 @ h1 + b; 20-step elementwise IndRNN scan
    //      (time-constant input) -> g_d0. Weights already in registers.
    {
#pragma unroll
        for (int i = tid; i < H; i += BLK) s_vec[i] = g_h1[i];   // coherent
        __syncthreads();
        const float4* s4 = (const float4*)s_vec + half * 128;
        float4 v0 = s4[lane], v1 = s4[32 + lane], v2 = s4[64 + lane], v3 = s4[96 + lane];
        float acc = 0.0f;
        acc = fmaf(wa.x, v0.x, acc); acc = fmaf(wa.y, v0.y, acc);
        acc = fmaf(wa.z, v0.z, acc); acc = fmaf(wa.w, v0.w, acc);
        acc = fmaf(wb.x, v1.x, acc); acc = fmaf(wb.y, v1.y, acc);
        acc = fmaf(wb.z, v1.z, acc); acc = fmaf(wb.w, v1.w, acc);
        acc = fmaf(wc.x, v2.x, acc); acc = fmaf(wc.y, v2.y, acc);
        acc = fmaf(wc.z, v2.z, acc); acc = fmaf(wc.w, v2.w, acc);
        acc = fmaf(wd.x, v3.x, acc); acc = fmaf(wd.y, v3.y, acc);
        acc = fmaf(wd.z, v3.z, acc); acc = fmaf(wd.w, v3.w, acc);
        acc = warp_reduce(acc);
        if (lane == 0) s_part[warp] = acc;
        __syncthreads();
        if (tid < 8) {
            const int g = blockIdx.x * 8 + tid;
            const float pre = s_part[tid] + s_part[tid + 8] + dec_b0[g];
            const float uu = dec_u0[g];
            float d = 0.0f;
#pragma unroll
            for (int t = 0; t < T; t++) {
                d = fmaxf(fmaf(uu, d, pre), 0.0f);
                g_d0[t * H + g] = d;
            }
        }
    }
    grid_barrier();

    // ---- Phase 3: pre1[t][h] = dec_w1[h] . d0[t] + b[h]  (GEMM 20x1024x1024).
    // 16 warps = 4 row-pairs x 4 t-quarters: 2 rows x 5 timesteps per warp.
    // Per j: 7 independent LDG.128 then 40 FMAs; ~60 regs, no spills at 128 cap.
    {
        const int rp = warp & 3;           // row pair within block's 8 rows
        const int tq = warp >> 2;          // t-quarter: t in [tq*5, tq*5+5)
        const int h0 = blockIdx.x * 8 + rp * 2;
        const float4* w0r = (const float4*)(dec_w1 + (size_t)h0 * H);
        const float4* w1r = w0r + (H / 4);
        const float4* d04 = (const float4*)g_d0 + tq * 5 * (H / 4);   // coherent

        float acc0[5], acc1[5];
#pragma unroll
        for (int t = 0; t < 5; t++) { acc0[t] = 0.0f; acc1[t] = 0.0f; }

#pragma unroll
        for (int j = 0; j < 8; j++) {
            const int c = j * 32 + lane;
            float4 a = __ldg(w0r + c);     // weights: kernel-constant, __ldg OK
            float4 q = __ldg(w1r + c);
            float4 v[5];
#pragma unroll
            for (int t = 0; t < 5; t++) v[t] = d04[t * (H / 4) + c];
#pragma unroll
            for (int t = 0; t < 5; t++) {
                acc0[t] = fmaf(a.x, v[t].x, acc0[t]); acc0[t] = fmaf(a.y, v[t].y, acc0[t]);
                acc0[t] = fmaf(a.z, v[t].z, acc0[t]); acc0[t] = fmaf(a.w, v[t].w, acc0[t]);
                acc1[t] = fmaf(q.x, v[t].x, acc1[t]); acc1[t] = fmaf(q.y, v[t].y, acc1[t]);
                acc1[t] = fmaf(q.z, v[t].z, acc1[t]); acc1[t] = fmaf(q.w, v[t].w, acc1[t]);
            }
        }
#pragma unroll
        for (int t = 0; t < 5; t++) {
            acc0[t] = warp_reduce(acc0[t]);
            acc1[t] = warp_reduce(acc1[t]);
        }
        if (lane == 0) {
#pragma unroll
            for (int t = 0; t < 5; t++) s_pre[rp * 2][tq * 5 + t] = acc0[t];
        }
        if (lane == 1) {
#pragma unroll
            for (int t = 0; t < 5; t++) s_pre[rp * 2 + 1][tq * 5 + t] = acc1[t];
        }
        __syncthreads();
        if (tid < 8) {
            const int hh = blockIdx.x * 8 + tid;
            const float bb = dec_b1[hh], uu = dec_u1[hh];
            float d = 0.0f;
#pragma unroll
            for (int t = 0; t < T; t++) {
                d = fmaxf(fmaf(uu, d, s_pre[tid][t] + bb), 0.0f);
                g_d1[t * H + hh] = d;
            }
        }
    }
    grid_barrier();

    // ---- Phase 4: predict[t,k] = out_w[k] . d1[t] + out_b[k]. 40 outputs over
    //      5 blocks; 2 warps per output (K-halves). g_d1 read coherently.
    if (blockIdx.x < 5) {
        const int o = blockIdx.x * 8 + row;           // 0..39, == t*2+k
        const int t = o >> 1, k = o & 1;
        const float4* wr = (const float4*)(out_w + (size_t)k * H) + half * 128;
        const float4* dr = (const float4*)(g_d1 + (size_t)t * H) + half * 128;
        float acc = 0.0f;
#pragma unroll
        for (int j = 0; j < 4; j++) {
            const int c = j * 32 + lane;
            float4 a = __ldg(wr + c);
            float4 v = dr[c];                          // coherent load
            acc = fmaf(a.x, v.x, acc); acc = fmaf(a.y, v.y, acc);
            acc = fmaf(a.z, v.z, acc); acc = fmaf(a.w, v.w, acc);
        }
        acc = warp_reduce(acc);
        if (lane == 0) s_part[warp] = acc;
        __syncthreads();
        if (tid < 8)
            out[blockIdx.x * 8 + tid] =
                s_part[tid] + s_part[tid + 8] + out_b[(blockIdx.x * 8 + tid) & 1];
    }
}

extern "C" void kernel_launch(void* const* d_in, const int* in_sizes, int n_in,
                              void* d_out, int out_size) {
    const float* x      = (const float*)d_in[0];
    const float* enc_w0 = (const float*)d_in[1];
    // d_in[2] = enc_u0: unused (only t=0 encoder state needed, h_{-1}=0)
    const float* enc_b0 = (const float*)d_in[3];
    const float* enc_w1 = (const float*)d_in[4];
    // d_in[5] = enc_u1: unused
    const float* enc_b1 = (const float*)d_in[6];
    const float* dec_w0 = (const float*)d_in[7];
    const float* dec_u0 = (const float*)d_in[8];
    const float* dec_b0 = (const float*)d_in[9];
    const float* dec_w1 = (const float*)d_in[10];
    const float* dec_u1 = (const float*)d_in[11];
    const float* dec_b1 = (const float*)d_in[12];
    const float* out_w  = (const float*)d_in[13];
    const float* out_b  = (const float*)d_in[14];
    float* out = (float*)d_out;

    fused_net<<<GRID, BLK>>>(x, enc_w0, enc_b0, enc_w1, enc_b1,
                             dec_w0, dec_u0, dec_b0,
                             dec_w1, dec_u1, dec_b1,
                             out_w, out_b, out);
}